// round 2
// baseline (speedup 1.0000x reference)
#include <cuda_runtime.h>
#include <cuda_bf16.h>
#include <math.h>

// ---------------- problem constants ----------------
#define V_   16384
#define D_   768
#define H_   12
#define DH_  64
#define L_   2
#define F_   3072
#define CC_  64      // chunk size
#define NB_  64
#define B_   2
#define S_   2048
#define NC_  (S_ / CC_)   // 32
#define CE_  (2 * CC_)    // 128 extended keys (prev chunk + current)
#define BS_  (B_ * S_)    // 4096 rows

// ---------------- scratch (device globals; no allocation allowed) ----------------
__device__ float g_x   [BS_ * D_];
__device__ float g_xn  [BS_ * D_];
__device__ float g_qk  [BS_ * D_];
__device__ float g_v   [BS_ * D_];
__device__ float g_att [BS_ * D_];
__device__ float g_h1  [BS_ * F_];
__device__ int   g_key [B_ * H_ * S_];
__device__ int   g_ord [B_ * H_ * S_];

// ---------------- embedding ----------------
__global__ void embed_kernel(const int* __restrict__ ids,
                             const float* __restrict__ emb,
                             const float* __restrict__ pos,
                             float* __restrict__ x) {
    int i = blockIdx.x * blockDim.x + threadIdx.x;
    if (i >= BS_ * D_) return;
    int d = i % D_;
    int row = i / D_;
    int s = row % S_;
    x[i] = emb[(size_t)ids[row] * D_ + d] + pos[(size_t)s * D_ + d];
}

// ---------------- layernorm (one block per row of 768) ----------------
__global__ void ln_kernel(const float* __restrict__ x, float* __restrict__ y,
                          const float* __restrict__ g, const float* __restrict__ b) {
    int row = blockIdx.x;
    const float* xr = x + (size_t)row * D_;
    float*       yr = y + (size_t)row * D_;
    int t = threadIdx.x;
    float v0 = xr[t], v1 = xr[t + 256], v2 = xr[t + 512];

    __shared__ float red[256];
    red[t] = v0 + v1 + v2;
    __syncthreads();
    #pragma unroll
    for (int o = 128; o > 0; o >>= 1) {
        if (t < o) red[t] += red[t + o];
        __syncthreads();
    }
    float mean = red[0] * (1.0f / D_);
    __syncthreads();

    float d0 = v0 - mean, d1 = v1 - mean, d2 = v2 - mean;
    red[t] = d0 * d0 + d1 * d1 + d2 * d2;
    __syncthreads();
    #pragma unroll
    for (int o = 128; o > 0; o >>= 1) {
        if (t < o) red[t] += red[t + o];
        __syncthreads();
    }
    float inv = rsqrtf(red[0] * (1.0f / D_) + 1e-12f);

    yr[t]       = d0 * inv * g[t]       + b[t];
    yr[t + 256] = d1 * inv * g[t + 256] + b[t + 256];
    yr[t + 512] = d2 * inv * g[t + 512] + b[t + 512];
}

// ---------------- GEMM: C[M,N] (+)= act(A[M,K] @ B[K,N] + bias) ----------------
// 128x128 tile, BK=16, 256 threads, 8x8 micro-tile. All dims multiple of 128/16.
__device__ __forceinline__ float gelu_f(float x) {
    float x3 = x * x * x;
    return 0.5f * x * (1.0f + tanhf(0.7978845608028654f * (x + 0.044715f * x3)));
}

template <bool ADD, bool BIAS, bool GELU>
__global__ void __launch_bounds__(256)
sgemm_kernel(const float* __restrict__ A, const float* __restrict__ B,
             const float* __restrict__ bias, float* __restrict__ C,
             int M, int N, int K) {
    __shared__ float As[16][132];
    __shared__ float Bs[16][128];

    const int t  = threadIdx.x;
    const int tx = t & 15;       // 0..15  -> col group
    const int ty = t >> 4;       // 0..15  -> row group
    const int m0 = blockIdx.y * 128;
    const int n0 = blockIdx.x * 128;

    float acc[8][8];
    #pragma unroll
    for (int i = 0; i < 8; i++)
        #pragma unroll
        for (int j = 0; j < 8; j++) acc[i][j] = 0.0f;

    for (int k0 = 0; k0 < K; k0 += 16) {
        // A tile: 128 rows x 16 k, stored transposed As[k][m]
        #pragma unroll
        for (int l = 0; l < 2; l++) {
            int idx = t + l * 256;            // 0..511 float4s
            int r   = idx >> 2;               // row within tile
            int kc  = (idx & 3) * 4;
            float4 av = *(const float4*)(A + (size_t)(m0 + r) * K + k0 + kc);
            As[kc + 0][r] = av.x;
            As[kc + 1][r] = av.y;
            As[kc + 2][r] = av.z;
            As[kc + 3][r] = av.w;
        }
        // B tile: 16 k x 128 n
        #pragma unroll
        for (int l = 0; l < 2; l++) {
            int idx = t + l * 256;
            int r   = idx >> 5;
            int c   = (idx & 31) * 4;
            *(float4*)(&Bs[r][c]) = *(const float4*)(B + (size_t)(k0 + r) * N + n0 + c);
        }
        __syncthreads();

        #pragma unroll
        for (int kk = 0; kk < 16; kk++) {
            float a[8], bb[8];
            #pragma unroll
            for (int i = 0; i < 8; i++) a[i]  = As[kk][ty * 8 + i];
            #pragma unroll
            for (int j = 0; j < 8; j++) bb[j] = Bs[kk][tx * 8 + j];
            #pragma unroll
            for (int i = 0; i < 8; i++)
                #pragma unroll
                for (int j = 0; j < 8; j++)
                    acc[i][j] = fmaf(a[i], bb[j], acc[i][j]);
        }
        __syncthreads();
    }

    #pragma unroll
    for (int i = 0; i < 8; i++) {
        int row = m0 + ty * 8 + i;
        #pragma unroll
        for (int j = 0; j < 8; j++) {
            int col = n0 + tx * 8 + j;
            float v = acc[i][j];
            if (BIAS) v += bias[col];
            if (GELU) v = gelu_f(v);
            size_t o = (size_t)row * N + col;
            if (ADD) C[o] += v; else C[o] = v;
        }
    }
}

// ---------------- LSH bucket ids ----------------
// one thread per (b,h,s): rotated = q @ rot[h], bucket = argmax([r, -r])
__global__ void bucket_kernel(const float* __restrict__ qk,
                              const float* __restrict__ rot,   // [H,DH,32] (layer offset applied)
                              int* __restrict__ sortkey) {
    int idx = blockIdx.x * blockDim.x + threadIdx.x;
    if (idx >= B_ * H_ * S_) return;
    int s = idx % S_;
    int h = (idx / S_) % H_;
    int b = idx / (S_ * H_);

    const float* q = qk + ((size_t)(b * S_ + s)) * D_ + h * DH_;
    float r[32];
    #pragma unroll
    for (int j = 0; j < 32; j++) r[j] = 0.0f;
    for (int d = 0; d < DH_; d++) {
        float qd = q[d];
        const float* rp = rot + ((size_t)h * DH_ + d) * 32;
        #pragma unroll
        for (int j = 0; j < 32; j++) r[j] = fmaf(qd, rp[j], r[j]);
    }
    float best = r[0];
    int bid = 0;
    #pragma unroll
    for (int j = 1; j < 32; j++)
        if (r[j] > best) { best = r[j]; bid = j; }
    #pragma unroll
    for (int j = 0; j < 32; j++) {
        float v = -r[j];
        if (v > best) { best = v; bid = 32 + j; }
    }
    sortkey[idx] = bid * S_ + s;   // unique keys -> stable
}

// ---------------- bitonic argsort of 2048 keys per (b,h) ----------------
__global__ void __launch_bounds__(1024)
sort_kernel(const int* __restrict__ sortkey, int* __restrict__ order) {
    int row = blockIdx.x;
    __shared__ int k[2048];
    __shared__ int vv[2048];
    const int* kr = sortkey + (size_t)row * S_;
    int t = threadIdx.x;
    for (int i = t; i < 2048; i += 1024) { k[i] = kr[i]; vv[i] = i; }

    for (int size = 2; size <= 2048; size <<= 1) {
        for (int stride = size >> 1; stride > 0; stride >>= 1) {
            __syncthreads();
            int pos = 2 * t - (t & (stride - 1));
            bool asc = ((pos & size) == 0);
            int a = k[pos], b = k[pos + stride];
            bool sw = asc ? (a > b) : (a < b);
            if (sw) {
                k[pos] = b;  k[pos + stride] = a;
                int va = vv[pos]; vv[pos] = vv[pos + stride]; vv[pos + stride] = va;
            }
        }
    }
    __syncthreads();
    int* orow = order + (size_t)row * S_;
    for (int i = t; i < 2048; i += 1024) orow[i] = vv[i];
}

// ---------------- chunked LSH attention ----------------
struct AttnSmem {
    float qs[CC_][DH_];        // 16 KB
    float ks[CE_][DH_ + 1];    // 33.3 KB (padded, normalized keys)
    float vs[CE_][DH_ + 1];    // 33.3 KB
    float arow[8][CE_];        // per-warp softmax row scratch
    int kpos[CE_], kb[CE_], km[CE_];
    int qpos[CC_], qb[CC_];
};

__global__ void __launch_bounds__(256)
attn_kernel(const float* __restrict__ qk, const float* __restrict__ v,
            const int* __restrict__ sortkey, const int* __restrict__ order,
            const int* __restrict__ amask, float* __restrict__ att_out) {
    extern __shared__ char sraw[];
    AttnSmem& s = *reinterpret_cast<AttnSmem*>(sraw);

    const int n = blockIdx.x, h = blockIdx.y, b = blockIdx.z;
    const int bh = b * H_ + h;
    const int* ord  = order   + (size_t)bh * S_;
    const int* skey = sortkey + (size_t)bh * S_;
    const int t = threadIdx.x;
    const int prev = (n + NC_ - 1) % NC_;

    // gather metadata for extended keys + queries
    for (int e = t; e < CE_; e += 256) {
        int si = (e < CC_) ? prev * CC_ + e : n * CC_ + (e - CC_);
        int p = ord[si];
        s.kpos[e] = p;
        s.kb[e]   = skey[p] >> 11;       // bucket = key / 2048
        s.km[e]   = amask[b * S_ + p];
    }
    for (int r = t; r < CC_; r += 256) {
        int p = ord[n * CC_ + r];
        s.qpos[r] = p;
        s.qb[r]   = skey[p] >> 11;
    }
    __syncthreads();

    // gather k/v/q rows through 'order'
    for (int idx = t; idx < CE_ * DH_; idx += 256) {
        int e = idx >> 6, d = idx & 63;
        size_t off = ((size_t)(b * S_ + s.kpos[e])) * D_ + h * DH_ + d;
        s.ks[e][d] = qk[off];
        s.vs[e][d] = v[off];
    }
    for (int idx = t; idx < CC_ * DH_; idx += 256) {
        int r = idx >> 6, d = idx & 63;
        s.qs[r][d] = qk[((size_t)(b * S_ + s.qpos[r])) * D_ + h * DH_ + d];
    }
    __syncthreads();

    // key = sqk / (||sqk|| + 1e-6)
    if (t < CE_) {
        float ss = 0.0f;
        #pragma unroll
        for (int d = 0; d < DH_; d++) ss = fmaf(s.ks[t][d], s.ks[t][d], ss);
        float sc = 1.0f / (sqrtf(ss) + 1e-6f);
        #pragma unroll
        for (int d = 0; d < DH_; d++) s.ks[t][d] *= sc;
    }
    __syncthreads();

    const int w = t >> 5, lane = t & 31;
    for (int rr = 0; rr < 8; rr++) {
        const int r  = w * 8 + rr;
        const int pq = s.qpos[r];
        const int bq = s.qb[r];

        float dv[4];
        #pragma unroll
        for (int c = 0; c < 4; c++) {
            int col = lane + 32 * c;
            float acc = 0.0f;
            #pragma unroll
            for (int d = 0; d < DH_; d++) acc = fmaf(s.qs[r][d], s.ks[col][d], acc);
            acc *= 0.125f;                       // 1/sqrt(64)
            if (bq != s.kb[col]) acc = -1e9f;    // cross-bucket
            if (s.km[col] <= 0)  acc = -1e9f;    // attention mask
            if (pq == s.kpos[col]) acc = -1e5f;  // soft self-mask (overrides)
            dv[c] = acc;
        }
        // warp softmax over 128
        float mx = fmaxf(fmaxf(dv[0], dv[1]), fmaxf(dv[2], dv[3]));
        #pragma unroll
        for (int o = 16; o > 0; o >>= 1) mx = fmaxf(mx, __shfl_xor_sync(0xffffffffu, mx, o));
        float sum = 0.0f;
        #pragma unroll
        for (int c = 0; c < 4; c++) sum += __expf(dv[c] - mx) == 0.0f ? expf(dv[c] - mx) : expf(dv[c] - mx);
        #pragma unroll
        for (int o = 16; o > 0; o >>= 1) sum += __shfl_xor_sync(0xffffffffu, sum, o);
        float inv = 1.0f / sum;
        #pragma unroll
        for (int c = 0; c < 4; c++) s.arow[w][lane + 32 * c] = expf(dv[c] - mx) * inv;
        __syncwarp();

        // out = attn @ v_ext : lane owns dims (lane, lane+32)
        float o0 = 0.0f, o1 = 0.0f;
        #pragma unroll 4
        for (int kk = 0; kk < CE_; kk++) {
            float a = s.arow[w][kk];
            o0 = fmaf(a, s.vs[kk][lane],      o0);
            o1 = fmaf(a, s.vs[kk][lane + 32], o1);
        }
        size_t obase = ((size_t)(b * S_ + pq)) * D_ + h * DH_;
        att_out[obase + lane]      = o0;   // scatter (unsort) directly
        att_out[obase + lane + 32] = o1;
        __syncwarp();
    }
}

// ---------------- host orchestration ----------------
extern "C" void kernel_launch(void* const* d_in, const int* in_sizes, int n_in,
                              void* d_out, int out_size) {
    const int*   ids   = (const int*)  d_in[0];
    const int*   amask = (const int*)  d_in[1];
    const float* emb   = (const float*)d_in[2];
    const float* pose  = (const float*)d_in[3];
    const float* rot   = (const float*)d_in[4];
    const float* Wqk   = (const float*)d_in[5];
    const float* Wv    = (const float*)d_in[6];
    const float* Wo    = (const float*)d_in[7];
    const float* ln1g  = (const float*)d_in[8];
    const float* ln1b  = (const float*)d_in[9];
    const float* ln2g  = (const float*)d_in[10];
    const float* ln2b  = (const float*)d_in[11];
    const float* W1    = (const float*)d_in[12];
    const float* b1    = (const float*)d_in[13];
    const float* W2    = (const float*)d_in[14];
    const float* b2    = (const float*)d_in[15];
    const float* lnfg  = (const float*)d_in[16];
    const float* lnfb  = (const float*)d_in[17];
    const float* Wlm   = (const float*)d_in[18];
    const float* blm   = (const float*)d_in[19];
    float* out = (float*)d_out;

    float *x, *xn, *qk, *v, *att, *h1;
    int *key, *ord;
    cudaGetSymbolAddress((void**)&x,   g_x);
    cudaGetSymbolAddress((void**)&xn,  g_xn);
    cudaGetSymbolAddress((void**)&qk,  g_qk);
    cudaGetSymbolAddress((void**)&v,   g_v);
    cudaGetSymbolAddress((void**)&att, g_att);
    cudaGetSymbolAddress((void**)&h1,  g_h1);
    cudaGetSymbolAddress((void**)&key, g_key);
    cudaGetSymbolAddress((void**)&ord, g_ord);

    static bool attr_set = false;
    if (!attr_set) {
        cudaFuncSetAttribute(attn_kernel, cudaFuncAttributeMaxDynamicSharedMemorySize,
                             (int)sizeof(AttnSmem));
        attr_set = true;
    }

    // embeddings
    {
        int total = BS_ * D_;
        embed_kernel<<<(total + 255) / 256, 256>>>(ids, emb, pose, x);
    }

    for (int l = 0; l < L_; l++) {
        // LN1
        ln_kernel<<<BS_, 256>>>(x, xn, ln1g + l * D_, ln1b + l * D_);
        // qk / v projections
        {
            dim3 grid(D_ / 128, BS_ / 128);
            sgemm_kernel<false, false, false><<<grid, 256>>>(xn, Wqk + (size_t)l * D_ * D_, nullptr, qk, BS_, D_, D_);
            sgemm_kernel<false, false, false><<<grid, 256>>>(xn, Wv  + (size_t)l * D_ * D_, nullptr, v,  BS_, D_, D_);
        }
        // buckets + sort
        bucket_kernel<<<(B_ * H_ * S_ + 255) / 256, 256>>>(qk, rot + (size_t)l * H_ * DH_ * (NB_ / 2), key);
        sort_kernel<<<B_ * H_, 1024>>>(key, ord);
        // chunked attention (gathers through order, scatters unsorted output)
        {
            dim3 grid(NC_, H_, B_);
            attn_kernel<<<grid, 256, sizeof(AttnSmem)>>>(qk, v, key, ord, amask, att);
        }
        // x += att @ Wo
        {
            dim3 grid(D_ / 128, BS_ / 128);
            sgemm_kernel<true, false, false><<<grid, 256>>>(att, Wo + (size_t)l * D_ * D_, nullptr, x, BS_, D_, D_);
        }
        // FFN
        ln_kernel<<<BS_, 256>>>(x, xn, ln2g + l * D_, ln2b + l * D_);
        {
            dim3 grid1(F_ / 128, BS_ / 128);
            sgemm_kernel<false, true, true><<<grid1, 256>>>(xn, W1 + (size_t)l * D_ * F_, b1 + (size_t)l * F_, h1, BS_, F_, D_);
            dim3 grid2(D_ / 128, BS_ / 128);
            sgemm_kernel<true, true, false><<<grid2, 256>>>(h1, W2 + (size_t)l * F_ * D_, b2 + (size_t)l * D_, x, BS_, D_, F_);
        }
    }

    // final LN + LM head
    ln_kernel<<<BS_, 256>>>(x, xn, lnfg, lnfb);
    {
        dim3 grid(V_ / 128, BS_ / 128);
        sgemm_kernel<false, true, false><<<grid, 256>>>(xn, Wlm, blm, out, BS_, V_, D_);
    }
}

// round 6
// speedup vs baseline: 1.5177x; 1.5177x over previous
#include <cuda_runtime.h>
#include <cuda_bf16.h>
#include <math.h>
#include <stdint.h>

// ---------------- problem constants ----------------
#define V_   16384
#define D_   768
#define H_   12
#define DH_  64
#define L_   2
#define F_   3072
#define CC_  64
#define NB_  64
#define B_   2
#define S_   2048
#define NC_  (S_ / CC_)   // 32
#define CE_  (2 * CC_)    // 128
#define BS_  (B_ * S_)    // 4096

// ---------------- scratch (device globals) ----------------
__device__ float g_x   [BS_ * D_];
__device__ float g_xn  [BS_ * D_];
__device__ float g_xnh [BS_ * D_];
__device__ float g_xnl [BS_ * D_];
__device__ float g_qk  [BS_ * D_];
__device__ float g_v   [BS_ * D_];
__device__ float g_att [BS_ * D_];
__device__ float g_atth[BS_ * D_];
__device__ float g_attl[BS_ * D_];
__device__ float g_h1  [BS_ * F_];
__device__ float g_h1h [BS_ * F_];
__device__ float g_h1l [BS_ * F_];
__device__ int   g_key [B_ * H_ * S_];
__device__ int   g_ord [B_ * H_ * S_];
// transposed weights ([N,K]) split into tf32 hi/lo parts
__device__ float g_WqkTh[L_ * D_ * D_];
__device__ float g_WqkTl[L_ * D_ * D_];
__device__ float g_WvTh [L_ * D_ * D_];
__device__ float g_WvTl [L_ * D_ * D_];
__device__ float g_WoTh [L_ * D_ * D_];
__device__ float g_WoTl [L_ * D_ * D_];
__device__ float g_W1Th [L_ * D_ * F_];
__device__ float g_W1Tl [L_ * D_ * F_];
__device__ float g_W2Th [L_ * F_ * D_];
__device__ float g_W2Tl [L_ * F_ * D_];
__device__ float g_WlmTh[(size_t)V_ * D_];

// =================== PTX helpers (base sm_103 target only) ===================
__device__ __forceinline__ uint32_t smem_u32(const void* p) {
    uint32_t r;
    asm("{ .reg .u64 t; cvta.to.shared.u64 t, %1; cvt.u32.u64 %0, t; }"
        : "=r"(r) : "l"(p));
    return r;
}
__device__ __forceinline__ uint32_t cvt_tf32(float f) {
    uint32_t r;
    asm("cvt.rna.tf32.f32 %0, %1;" : "=r"(r) : "f"(f));
    return r;
}
__device__ __forceinline__ float cvt_tf32f(float f) {
    return __uint_as_float(cvt_tf32(f));
}
__device__ __forceinline__ void ldsm_x4(uint32_t addr, uint32_t* r) {
    asm volatile("ldmatrix.sync.aligned.m8n8.x4.shared.b16 {%0,%1,%2,%3}, [%4];"
                 : "=r"(r[0]), "=r"(r[1]), "=r"(r[2]), "=r"(r[3]) : "r"(addr));
}
__device__ __forceinline__ void mma_tf32(float* c, const uint32_t* a, const uint32_t* b) {
    asm volatile("mma.sync.aligned.m16n8k8.row.col.f32.tf32.tf32.f32 "
                 "{%0,%1,%2,%3}, {%4,%5,%6,%7}, {%8,%9}, {%0,%1,%2,%3};"
                 : "+f"(c[0]), "+f"(c[1]), "+f"(c[2]), "+f"(c[3])
                 : "r"(a[0]), "r"(a[1]), "r"(a[2]), "r"(a[3]),
                   "r"(b[0]), "r"(b[1]));
}

// =================== elementwise / small kernels ===================
__global__ void embed_kernel(const int* __restrict__ ids,
                             const float* __restrict__ emb,
                             const float* __restrict__ pos,
                             float* __restrict__ x) {
    int i = blockIdx.x * blockDim.x + threadIdx.x;
    if (i >= BS_ * D_) return;
    int d = i % D_;
    int row = i / D_;
    int s = row % S_;
    x[i] = emb[(size_t)ids[row] * D_ + d] + pos[(size_t)s * D_ + d];
}

__global__ void ln_kernel(const float* __restrict__ x, float* __restrict__ y,
                          const float* __restrict__ g, const float* __restrict__ b) {
    int row = blockIdx.x;
    const float* xr = x + (size_t)row * D_;
    float*       yr = y + (size_t)row * D_;
    int t = threadIdx.x;
    float v0 = xr[t], v1 = xr[t + 256], v2 = xr[t + 512];

    __shared__ float red[256];
    red[t] = v0 + v1 + v2;
    __syncthreads();
    #pragma unroll
    for (int o = 128; o > 0; o >>= 1) {
        if (t < o) red[t] += red[t + o];
        __syncthreads();
    }
    float mean = red[0] * (1.0f / D_);
    __syncthreads();

    float d0 = v0 - mean, d1 = v1 - mean, d2 = v2 - mean;
    red[t] = d0 * d0 + d1 * d1 + d2 * d2;
    __syncthreads();
    #pragma unroll
    for (int o = 128; o > 0; o >>= 1) {
        if (t < o) red[t] += red[t + o];
        __syncthreads();
    }
    float inv = rsqrtf(red[0] * (1.0f / D_) + 1e-12f);

    yr[t]       = d0 * inv * g[t]       + b[t];
    yr[t + 256] = d1 * inv * g[t + 256] + b[t + 256];
    yr[t + 512] = d2 * inv * g[t + 512] + b[t + 512];
}

// split src into tf32 hi + lo (vectorized float4)
__global__ void split_kernel(const float* __restrict__ src,
                             float* __restrict__ hi, float* __restrict__ lo,
                             int n4) {
    int i = blockIdx.x * blockDim.x + threadIdx.x;
    if (i >= n4) return;
    float4 v = ((const float4*)src)[i];
    float4 h = make_float4(cvt_tf32f(v.x), cvt_tf32f(v.y), cvt_tf32f(v.z), cvt_tf32f(v.w));
    ((float4*)hi)[i] = h;
    ((float4*)lo)[i] = make_float4(cvt_tf32f(v.x - h.x), cvt_tf32f(v.y - h.y),
                                   cvt_tf32f(v.z - h.z), cvt_tf32f(v.w - h.w));
}

__device__ __forceinline__ float gelu_f(float x) {
    float x3 = x * x * x;
    return 0.5f * x * (1.0f + tanhf(0.7978845608028654f * (x + 0.044715f * x3)));
}

// h1 = gelu(h1 + b1[col]), row-major [BS, F]
__global__ void gelu_bias_kernel(float* __restrict__ h, const float* __restrict__ b) {
    int i = blockIdx.x * blockDim.x + threadIdx.x;   // float4 index
    if (i >= BS_ * F_ / 4) return;
    int col4 = (i * 4) % F_;
    float4 v = ((float4*)h)[i];
    float4 bb = *(const float4*)(b + col4);
    v.x = gelu_f(v.x + bb.x);
    v.y = gelu_f(v.y + bb.y);
    v.z = gelu_f(v.z + bb.z);
    v.w = gelu_f(v.w + bb.w);
    ((float4*)h)[i] = v;
}

// transpose src[R,C] -> dst[C,R], splitting into tf32 hi (+ optional lo)
__global__ void transpose_split_kernel(const float* __restrict__ src,
                                       float* __restrict__ dhi,
                                       float* __restrict__ dlo,
                                       int R, int C) {
    __shared__ float tile[32][33];
    int c0 = blockIdx.x * 32, r0 = blockIdx.y * 32;
    int x = threadIdx.x, y = threadIdx.y;
    #pragma unroll
    for (int j = 0; j < 32; j += 8)
        tile[y + j][x] = src[(size_t)(r0 + y + j) * C + c0 + x];
    __syncthreads();
    #pragma unroll
    for (int j = 0; j < 32; j += 8) {
        float w  = tile[x][y + j];
        float hi = cvt_tf32f(w);
        size_t o = (size_t)(c0 + y + j) * R + r0 + x;
        dhi[o] = hi;
        if (dlo) dlo[o] = cvt_tf32f(w - hi);
    }
}

// =================== tf32 mma.sync GEMM (single pass) ===================
// C[M,N] (+)= A[M,K] @ Bt[N,K]^T (+ bias)
// 128x128 CTA tile, BK=16, 256 thr (warps 2x4, warp tile 64x32), dbl-buffered.
// A rounded to tf32 (rna) on smem store; Bt assumed pre-rounded.
#define BK_   16
#define SAS_  20   // padded row stride in floats

template <bool ADD, bool BIAS>
__global__ void __launch_bounds__(256, 2)
tgemm_kernel(const float* __restrict__ A, const float* __restrict__ Bt,
             const float* __restrict__ bias, float* __restrict__ C,
             int M, int N, int K) {
    __shared__ __align__(16) float As[2][128 * SAS_];
    __shared__ __align__(16) float Bs[2][128 * SAS_];

    const int t = threadIdx.x, lane = t & 31, wid = t >> 5;
    const int wm = wid & 1, wn = wid >> 1;            // 2 x 4 warp grid
    const int m0 = blockIdx.y * 128, n0 = blockIdx.x * 128;
    const int KT = K / BK_;

    const int grow = t >> 1;               // 0..127
    const int gcol = (t & 1) * 8;          // 0 or 8
    const float* pA = A  + (size_t)(m0 + grow) * K + gcol;
    const float* pB = Bt + (size_t)(n0 + grow) * K + gcol;
    float* sa_p0 = &As[0][grow * SAS_ + gcol];
    float* sb_p0 = &Bs[0][grow * SAS_ + gcol];

    const uint32_t as0 = smem_u32(&As[0][0]);
    const uint32_t bs0 = smem_u32(&Bs[0][0]);
    const uint32_t BUFD = 128 * SAS_ * 4;
    uint32_t a_addr[4], b_addr[2];
    {
        int ra = wm * 64 + (lane & 15);
        int ca = (lane >> 4) * 4;
        #pragma unroll
        for (int mt = 0; mt < 4; mt++)
            a_addr[mt] = as0 + (uint32_t)(((ra + mt * 16) * SAS_ + ca) * 4);
        int rb = wn * 32 + ((lane >> 4) * 8) + (lane & 7);
        int cb = ((lane >> 3) & 1) * 4;
        #pragma unroll
        for (int p = 0; p < 2; p++)
            b_addr[p] = bs0 + (uint32_t)(((rb + p * 16) * SAS_ + cb) * 4);
    }

    float acc[4][4][4];
    #pragma unroll
    for (int i = 0; i < 4; i++)
        #pragma unroll
        for (int j = 0; j < 4; j++)
            #pragma unroll
            for (int k = 0; k < 4; k++) acc[i][j][k] = 0.0f;

    float4 ra0, ra1, rb0, rb1;

    ra0 = *(const float4*)(pA);     ra1 = *(const float4*)(pA + 4);
    rb0 = *(const float4*)(pB);     rb1 = *(const float4*)(pB + 4);
    *(float4*)(sa_p0)     = make_float4(cvt_tf32f(ra0.x), cvt_tf32f(ra0.y), cvt_tf32f(ra0.z), cvt_tf32f(ra0.w));
    *(float4*)(sa_p0 + 4) = make_float4(cvt_tf32f(ra1.x), cvt_tf32f(ra1.y), cvt_tf32f(ra1.z), cvt_tf32f(ra1.w));
    *(float4*)(sb_p0)     = rb0;
    *(float4*)(sb_p0 + 4) = rb1;
    __syncthreads();

    for (int kt = 0; kt < KT; kt++) {
        const int buf = kt & 1;
        const uint32_t boff = (uint32_t)buf * BUFD;

        if (kt + 1 < KT) {
            const int k0 = (kt + 1) * BK_;
            ra0 = *(const float4*)(pA + k0);     ra1 = *(const float4*)(pA + k0 + 4);
            rb0 = *(const float4*)(pB + k0);     rb1 = *(const float4*)(pB + k0 + 4);
        }

        #pragma unroll
        for (int ks = 0; ks < 2; ks++) {
            uint32_t af[4][4], bf[2][4];
            #pragma unroll
            for (int mt = 0; mt < 4; mt++)
                ldsm_x4(a_addr[mt] + boff + ks * 32, af[mt]);
            #pragma unroll
            for (int p = 0; p < 2; p++)
                ldsm_x4(b_addr[p] + boff + ks * 32, bf[p]);
            #pragma unroll
            for (int mt = 0; mt < 4; mt++)
                #pragma unroll
                for (int nt = 0; nt < 4; nt++)
                    mma_tf32(acc[mt][nt], af[mt], &bf[nt >> 1][(nt & 1) * 2]);
        }

        if (kt + 1 < KT) {
            float* sa = sa_p0 + (buf ^ 1) * (128 * SAS_);
            float* sb = sb_p0 + (buf ^ 1) * (128 * SAS_);
            *(float4*)(sa)     = make_float4(cvt_tf32f(ra0.x), cvt_tf32f(ra0.y), cvt_tf32f(ra0.z), cvt_tf32f(ra0.w));
            *(float4*)(sa + 4) = make_float4(cvt_tf32f(ra1.x), cvt_tf32f(ra1.y), cvt_tf32f(ra1.z), cvt_tf32f(ra1.w));
            *(float4*)(sb)     = rb0;
            *(float4*)(sb + 4) = rb1;
        }
        __syncthreads();
    }

    #pragma unroll
    for (int mt = 0; mt < 4; mt++) {
        const int r0 = m0 + wm * 64 + mt * 16 + (lane >> 2);
        #pragma unroll
        for (int nt = 0; nt < 4; nt++) {
            const int c0 = n0 + wn * 32 + nt * 8 + (lane & 3) * 2;
            float2 v0 = make_float2(acc[mt][nt][0], acc[mt][nt][1]);
            float2 v1 = make_float2(acc[mt][nt][2], acc[mt][nt][3]);
            if (BIAS) {
                float b0 = bias[c0], b1 = bias[c0 + 1];
                v0.x += b0; v0.y += b1;
                v1.x += b0; v1.y += b1;
            }
            float* p0 = C + (size_t)r0 * N + c0;
            float* p1 = C + (size_t)(r0 + 8) * N + c0;
            if (ADD) {
                float2 o0 = *(float2*)p0, o1 = *(float2*)p1;
                v0.x += o0.x; v0.y += o0.y;
                v1.x += o1.x; v1.y += o1.y;
            }
            *(float2*)p0 = v0;
            *(float2*)p1 = v1;
        }
    }
}

// 3-term split GEMM driver: C (+)= A @ Bt^T computed as Ah*Bh + Ah*Bl + Al*Bh.
// biasOnFirst: bias added exactly once (first accumulating launch).
static void tgemm_split3(const float* Ah, const float* Al,
                         const float* Bh, const float* Bl,
                         const float* bias, float* C,
                         int M, int N, int K, bool addInto) {
    dim3 grid(N / 128, M / 128);
    if (addInto) {
        if (bias) tgemm_kernel<true, true ><<<grid, 256>>>(Ah, Bh, bias, C, M, N, K);
        else      tgemm_kernel<true, false><<<grid, 256>>>(Ah, Bh, nullptr, C, M, N, K);
    } else {
        if (bias) tgemm_kernel<false, true ><<<grid, 256>>>(Ah, Bh, bias, C, M, N, K);
        else      tgemm_kernel<false, false><<<grid, 256>>>(Ah, Bh, nullptr, C, M, N, K);
    }
    tgemm_kernel<true, false><<<grid, 256>>>(Ah, Bl, nullptr, C, M, N, K);
    tgemm_kernel<true, false><<<grid, 256>>>(Al, Bh, nullptr, C, M, N, K);
}

// =================== LSH bucket ids ===================
__global__ void bucket_kernel(const float* __restrict__ qk,
                              const float* __restrict__ rot,
                              int* __restrict__ sortkey) {
    int idx = blockIdx.x * blockDim.x + threadIdx.x;
    if (idx >= B_ * H_ * S_) return;
    int s = idx % S_;
    int h = (idx / S_) % H_;
    int b = idx / (S_ * H_);

    const float* q = qk + ((size_t)(b * S_ + s)) * D_ + h * DH_;
    float r[32];
    #pragma unroll
    for (int j = 0; j < 32; j++) r[j] = 0.0f;
    for (int d = 0; d < DH_; d++) {
        float qd = q[d];
        const float* rp = rot + ((size_t)h * DH_ + d) * 32;
        #pragma unroll
        for (int j = 0; j < 32; j++) r[j] = fmaf(qd, rp[j], r[j]);
    }
    float best = r[0];
    int bid = 0;
    #pragma unroll
    for (int j = 1; j < 32; j++)
        if (r[j] > best) { best = r[j]; bid = j; }
    #pragma unroll
    for (int j = 0; j < 32; j++) {
        float v = -r[j];
        if (v > best) { best = v; bid = 32 + j; }
    }
    sortkey[idx] = bid * S_ + s;
}

// =================== bitonic argsort (2048 keys per (b,h)) ===================
__global__ void __launch_bounds__(1024)
sort_kernel(const int* __restrict__ sortkey, int* __restrict__ order) {
    int row = blockIdx.x;
    __shared__ int k[2048];
    __shared__ int vv[2048];
    const int* kr = sortkey + (size_t)row * S_;
    int t = threadIdx.x;
    for (int i = t; i < 2048; i += 1024) { k[i] = kr[i]; vv[i] = i; }

    for (int size = 2; size <= 2048; size <<= 1) {
        for (int stride = size >> 1; stride > 0; stride >>= 1) {
            __syncthreads();
            int pos = 2 * t - (t & (stride - 1));
            bool asc = ((pos & size) == 0);
            int a = k[pos], b = k[pos + stride];
            bool sw = asc ? (a > b) : (a < b);
            if (sw) {
                k[pos] = b;  k[pos + stride] = a;
                int va = vv[pos]; vv[pos] = vv[pos + stride]; vv[pos + stride] = va;
            }
        }
    }
    __syncthreads();
    int* orow = order + (size_t)row * S_;
    for (int i = t; i < 2048; i += 1024) orow[i] = vv[i];
}

// =================== chunked LSH attention ===================
struct AttnSmem {
    float qs[CC_][DH_];
    float ks[CE_][DH_ + 1];
    float vs[CE_][DH_ + 1];
    float arow[8][CE_];
    int kpos[CE_], kb[CE_], km[CE_];
    int qpos[CC_], qb[CC_];
};

__global__ void __launch_bounds__(256)
attn_kernel(const float* __restrict__ qk, const float* __restrict__ v,
            const int* __restrict__ sortkey, const int* __restrict__ order,
            const int* __restrict__ amask, float* __restrict__ att_out) {
    extern __shared__ char sraw[];
    AttnSmem& s = *reinterpret_cast<AttnSmem*>(sraw);

    const int n = blockIdx.x, h = blockIdx.y, b = blockIdx.z;
    const int bh = b * H_ + h;
    const int* ord  = order   + (size_t)bh * S_;
    const int* skey = sortkey + (size_t)bh * S_;
    const int t = threadIdx.x;
    const int prev = (n + NC_ - 1) % NC_;

    for (int e = t; e < CE_; e += 256) {
        int si = (e < CC_) ? prev * CC_ + e : n * CC_ + (e - CC_);
        int p = ord[si];
        s.kpos[e] = p;
        s.kb[e]   = skey[p] >> 11;
        s.km[e]   = amask[b * S_ + p];
    }
    for (int r = t; r < CC_; r += 256) {
        int p = ord[n * CC_ + r];
        s.qpos[r] = p;
        s.qb[r]   = skey[p] >> 11;
    }
    __syncthreads();

    for (int idx = t; idx < CE_ * DH_; idx += 256) {
        int e = idx >> 6, d = idx & 63;
        size_t off = ((size_t)(b * S_ + s.kpos[e])) * D_ + h * DH_ + d;
        s.ks[e][d] = qk[off];
        s.vs[e][d] = v[off];
    }
    for (int idx = t; idx < CC_ * DH_; idx += 256) {
        int r = idx >> 6, d = idx & 63;
        s.qs[r][d] = qk[((size_t)(b * S_ + s.qpos[r])) * D_ + h * DH_ + d];
    }
    __syncthreads();

    if (t < CE_) {
        float ss = 0.0f;
        #pragma unroll
        for (int d = 0; d < DH_; d++) ss = fmaf(s.ks[t][d], s.ks[t][d], ss);
        float sc = 1.0f / (sqrtf(ss) + 1e-6f);
        #pragma unroll
        for (int d = 0; d < DH_; d++) s.ks[t][d] *= sc;
    }
    __syncthreads();

    const int w = t >> 5, lane = t & 31;
    for (int rr = 0; rr < 8; rr++) {
        const int r  = w * 8 + rr;
        const int pq = s.qpos[r];
        const int bq = s.qb[r];

        float dv[4];
        #pragma unroll
        for (int c = 0; c < 4; c++) {
            int col = lane + 32 * c;
            float acc = 0.0f;
            #pragma unroll
            for (int d = 0; d < DH_; d++) acc = fmaf(s.qs[r][d], s.ks[col][d], acc);
            acc *= 0.125f;
            if (bq != s.kb[col]) acc = -1e9f;
            if (s.km[col] <= 0)  acc = -1e9f;
            if (pq == s.kpos[col]) acc = -1e5f;
            dv[c] = acc;
        }
        float mx = fmaxf(fmaxf(dv[0], dv[1]), fmaxf(dv[2], dv[3]));
        #pragma unroll
        for (int o = 16; o > 0; o >>= 1) mx = fmaxf(mx, __shfl_xor_sync(0xffffffffu, mx, o));
        float sum = 0.0f;
        #pragma unroll
        for (int c = 0; c < 4; c++) sum += expf(dv[c] - mx);
        #pragma unroll
        for (int o = 16; o > 0; o >>= 1) sum += __shfl_xor_sync(0xffffffffu, sum, o);
        float inv = 1.0f / sum;
        #pragma unroll
        for (int c = 0; c < 4; c++) s.arow[w][lane + 32 * c] = expf(dv[c] - mx) * inv;
        __syncwarp();

        float o0 = 0.0f, o1 = 0.0f;
        #pragma unroll 4
        for (int kk = 0; kk < CE_; kk++) {
            float a = s.arow[w][kk];
            o0 = fmaf(a, s.vs[kk][lane],      o0);
            o1 = fmaf(a, s.vs[kk][lane + 32], o1);
        }
        size_t obase = ((size_t)(b * S_ + pq)) * D_ + h * DH_;
        att_out[obase + lane]      = o0;
        att_out[obase + lane + 32] = o1;
        __syncwarp();
    }
}

// =================== host orchestration ===================
extern "C" void kernel_launch(void* const* d_in, const int* in_sizes, int n_in,
                              void* d_out, int out_size) {
    const int*   ids   = (const int*)  d_in[0];
    const int*   amask = (const int*)  d_in[1];
    const float* emb   = (const float*)d_in[2];
    const float* pose  = (const float*)d_in[3];
    const float* rot   = (const float*)d_in[4];
    const float* Wqk   = (const float*)d_in[5];
    const float* Wv    = (const float*)d_in[6];
    const float* Wo    = (const float*)d_in[7];
    const float* ln1g  = (const float*)d_in[8];
    const float* ln1b  = (const float*)d_in[9];
    const float* ln2g  = (const float*)d_in[10];
    const float* ln2b  = (const float*)d_in[11];
    const float* W1    = (const float*)d_in[12];
    const float* b1    = (const float*)d_in[13];
    const float* W2    = (const float*)d_in[14];
    const float* b2    = (const float*)d_in[15];
    const float* lnfg  = (const float*)d_in[16];
    const float* lnfb  = (const float*)d_in[17];
    const float* Wlm   = (const float*)d_in[18];
    const float* blm   = (const float*)d_in[19];
    float* out = (float*)d_out;

    float *x, *xn, *xnh, *xnl, *qk, *v, *att, *atth, *attl, *h1, *h1h, *h1l;
    float *WqkTh, *WqkTl, *WvTh, *WvTl, *WoTh, *WoTl;
    float *W1Th, *W1Tl, *W2Th, *W2Tl, *WlmTh;
    int *key, *ord;
    cudaGetSymbolAddress((void**)&x,     g_x);
    cudaGetSymbolAddress((void**)&xn,    g_xn);
    cudaGetSymbolAddress((void**)&xnh,   g_xnh);
    cudaGetSymbolAddress((void**)&xnl,   g_xnl);
    cudaGetSymbolAddress((void**)&qk,    g_qk);
    cudaGetSymbolAddress((void**)&v,     g_v);
    cudaGetSymbolAddress((void**)&att,   g_att);
    cudaGetSymbolAddress((void**)&atth,  g_atth);
    cudaGetSymbolAddress((void**)&attl,  g_attl);
    cudaGetSymbolAddress((void**)&h1,    g_h1);
    cudaGetSymbolAddress((void**)&h1h,   g_h1h);
    cudaGetSymbolAddress((void**)&h1l,   g_h1l);
    cudaGetSymbolAddress((void**)&key,   g_key);
    cudaGetSymbolAddress((void**)&ord,   g_ord);
    cudaGetSymbolAddress((void**)&WqkTh, g_WqkTh);
    cudaGetSymbolAddress((void**)&WqkTl, g_WqkTl);
    cudaGetSymbolAddress((void**)&WvTh,  g_WvTh);
    cudaGetSymbolAddress((void**)&WvTl,  g_WvTl);
    cudaGetSymbolAddress((void**)&WoTh,  g_WoTh);
    cudaGetSymbolAddress((void**)&WoTl,  g_WoTl);
    cudaGetSymbolAddress((void**)&W1Th,  g_W1Th);
    cudaGetSymbolAddress((void**)&W1Tl,  g_W1Tl);
    cudaGetSymbolAddress((void**)&W2Th,  g_W2Th);
    cudaGetSymbolAddress((void**)&W2Tl,  g_W2Tl);
    cudaGetSymbolAddress((void**)&WlmTh, g_WlmTh);

    static bool attr_set = false;
    if (!attr_set) {
        cudaFuncSetAttribute(attn_kernel, cudaFuncAttributeMaxDynamicSharedMemorySize,
                             (int)sizeof(AttnSmem));
        attr_set = true;
    }

    // ---- pre-transpose + tf32-split weights ([N,K] hi/lo) ----
    {
        dim3 tb(32, 8);
        for (int l = 0; l < L_; l++) {
            size_t odd = (size_t)l * D_ * D_;
            size_t odf = (size_t)l * D_ * F_;
            transpose_split_kernel<<<dim3(D_ / 32, D_ / 32), tb>>>(Wqk + odd, WqkTh + odd, WqkTl + odd, D_, D_);
            transpose_split_kernel<<<dim3(D_ / 32, D_ / 32), tb>>>(Wv  + odd, WvTh  + odd, WvTl  + odd, D_, D_);
            transpose_split_kernel<<<dim3(D_ / 32, D_ / 32), tb>>>(Wo  + odd, WoTh  + odd, WoTl  + odd, D_, D_);
            transpose_split_kernel<<<dim3(F_ / 32, D_ / 32), tb>>>(W1  + odf, W1Th  + odf, W1Tl  + odf, D_, F_);
            transpose_split_kernel<<<dim3(D_ / 32, F_ / 32), tb>>>(W2  + odf, W2Th  + odf, W2Tl  + odf, F_, D_);
        }
        transpose_split_kernel<<<dim3(V_ / 32, D_ / 32), tb>>>(Wlm, WlmTh, nullptr, D_, V_);
    }

    embed_kernel<<<(BS_ * D_ + 255) / 256, 256>>>(ids, emb, pose, x);

    const int nXN4 = BS_ * D_ / 4;
    const int nH14 = BS_ * F_ / 4;

    for (int l = 0; l < L_; l++) {
        const size_t odd = (size_t)l * D_ * D_;
        const size_t odf = (size_t)l * D_ * F_;

        // LN1 + split activations
        ln_kernel<<<BS_, 256>>>(x, xn, ln1g + l * D_, ln1b + l * D_);
        split_kernel<<<(nXN4 + 255) / 256, 256>>>(xn, xnh, xnl, nXN4);

        // qk = xn @ Wqk (exact), v = xn @ Wv (exact)
        tgemm_split3(xnh, xnl, WqkTh + odd, WqkTl + odd, nullptr, qk, BS_, D_, D_, false);
        tgemm_split3(xnh, xnl, WvTh  + odd, WvTl  + odd, nullptr, v,  BS_, D_, D_, false);

        bucket_kernel<<<(B_ * H_ * S_ + 255) / 256, 256>>>(qk, rot + (size_t)l * H_ * DH_ * (NB_ / 2), key);
        sort_kernel<<<B_ * H_, 1024>>>(key, ord);
        {
            dim3 grid(NC_, H_, B_);
            attn_kernel<<<grid, 256, sizeof(AttnSmem)>>>(qk, v, key, ord, amask, att);
        }

        // x += att @ Wo (exact)
        split_kernel<<<(nXN4 + 255) / 256, 256>>>(att, atth, attl, nXN4);
        tgemm_split3(atth, attl, WoTh + odd, WoTl + odd, nullptr, x, BS_, D_, D_, true);

        // FFN (exact)
        ln_kernel<<<BS_, 256>>>(x, xn, ln2g + l * D_, ln2b + l * D_);
        split_kernel<<<(nXN4 + 255) / 256, 256>>>(xn, xnh, xnl, nXN4);
        tgemm_split3(xnh, xnl, W1Th + odf, W1Tl + odf, nullptr, h1, BS_, F_, D_, false);
        gelu_bias_kernel<<<(nH14 + 255) / 256, 256>>>(h1, b1 + (size_t)l * F_);
        split_kernel<<<(nH14 + 255) / 256, 256>>>(h1, h1h, h1l, nH14);
        tgemm_split3(h1h, h1l, W2Th + odf, W2Tl + odf, b2 + (size_t)l * D_, x, BS_, D_, F_, true);
    }

    // final LN + LM head (continuous endpoint -> single-pass tf32)
    ln_kernel<<<BS_, 256>>>(x, xn, lnfg, lnfb);
    {
        dim3 grid(V_ / 128, BS_ / 128);
        tgemm_kernel<false, true><<<grid, 256>>>(xn, WlmTh, blm, out, BS_, V_, D_);
    }
}